// round 2
// baseline (speedup 1.0000x reference)
#include <cuda_runtime.h>
#include <math.h>

// Shapes (fixed for this problem)
#define R_TOTAL 4096     // B*L
#define DQ      512
#define DC      256
#define MTOK    64
#define NHEADS  8
#define DHEAD   64
#define INNER   512      // NHEADS*DHEAD

// Scratch (no allocations allowed -> device globals)
__device__ float g_Q   [R_TOTAL * INNER];        // 8 MB
__device__ float g_Qk  [R_TOTAL * NHEADS * DC];  // 32 MB
__device__ float g_ctxA[R_TOTAL * NHEADS * DC];  // 32 MB
__device__ float g_O1  [R_TOTAL * INNER];        // 8 MB

// ---------------------------------------------------------------------------
// Generic tiled SGEMM: C[m,n] = sum_k A[m*lda+k] * B[k*sBk + n*sBn] (+bias[n])
// BM=128, BN=64, BK=16, 256 threads, 8x4 microtile.
// blockIdx.z = batch (head), with per-operand batch strides.
// ---------------------------------------------------------------------------
template<bool BKC, bool BIAS>
__global__ __launch_bounds__(256)
void sgemm_k(int M, int N, int K,
             const float* __restrict__ A, int lda, int batchA,
             const float* __restrict__ B, int sBk, int sBn, int batchB,
             float* __restrict__ C, int ldc, int batchC,
             const float* __restrict__ bias)
{
    const int BM = 128, BN = 64, BK = 16, TM = 8, TN = 4;
    __shared__ float As[BK][BM + 4];
    __shared__ float Bs[BK][BN + 4];

    A += (size_t)blockIdx.z * batchA;
    B += (size_t)blockIdx.z * batchB;
    C += (size_t)blockIdx.z * batchC;

    const int bm = blockIdx.y * BM;
    const int bn = blockIdx.x * BN;
    const int tid = threadIdx.x;
    const int tx = tid % (BN / TN);   // 0..15 -> n
    const int ty = tid / (BN / TN);   // 0..15 -> m

    float acc[TM][TN];
#pragma unroll
    for (int i = 0; i < TM; i++)
#pragma unroll
        for (int j = 0; j < TN; j++) acc[i][j] = 0.0f;

    for (int k0 = 0; k0 < K; k0 += BK) {
#pragma unroll
        for (int s = 0; s < 8; s++) {
            int i = tid + s * 256;
            int k = i % BK;
            int m = i / BK;
            As[k][m] = A[(size_t)(bm + m) * lda + k0 + k];
        }
#pragma unroll
        for (int s = 0; s < 4; s++) {
            int i = tid + s * 256;
            int k, n;
            if (BKC) { k = i % BK; n = i / BK; }       // B contiguous along k
            else     { n = i % BN; k = i / BN; }       // B contiguous along n
            Bs[k][n] = B[(size_t)(k0 + k) * sBk + (size_t)(bn + n) * sBn];
        }
        __syncthreads();

#pragma unroll
        for (int k = 0; k < BK; k++) {
            float a[TM], b[TN];
#pragma unroll
            for (int i = 0; i < TM; i++) a[i] = As[k][ty * TM + i];
#pragma unroll
            for (int j = 0; j < TN; j++) b[j] = Bs[k][tx * TN + j];
#pragma unroll
            for (int i = 0; i < TM; i++)
#pragma unroll
                for (int j = 0; j < TN; j++) acc[i][j] += a[i] * b[j];
        }
        __syncthreads();
    }

#pragma unroll
    for (int i = 0; i < TM; i++) {
        size_t row = (size_t)(bm + ty * TM + i) * ldc + bn + tx * TN;
#pragma unroll
        for (int j = 0; j < TN; j++) {
            float v = acc[i][j];
            if (BIAS) v += bias[bn + tx * TN + j];
            C[row + j] = v;
        }
    }
}

// ---------------------------------------------------------------------------
// Attention core: one CTA per (b,l) row. Reads the 64x256 context tile ONCE.
//   scores[h][m] = (Qk[h][:] . ctx[m][:]) * 0.125 + bias[m], masked
//   attn = softmax_m(scores)
//   ctxA[h][c]   = sum_m attn[h][m] * ctx[m][c]
// NOTE: mask arrives as int32 (bool promoted by harness).
// ---------------------------------------------------------------------------
#define CTX_LD 260                    // 256 + 4 pad (float4-aligned, bank-skewed)
#define SMEM_FLOATS (MTOK*CTX_LD + NHEADS*DC + MTOK*12 + NHEADS*MTOK)
#define ATTN_SMEM_BYTES (SMEM_FLOATS * 4)

__global__ __launch_bounds__(256)
void attn_core(const float* __restrict__ ctx,
               const int* __restrict__ mask,
               const float* __restrict__ bias)
{
    extern __shared__ float sm[];
    float* ctxs = sm;                         // [64][260]
    float* qs   = ctxs + MTOK * CTX_LD;       // [8][256]
    float* ssT  = qs + NHEADS * DC;           // attn transposed [64][12]
    float* sc   = ssT + MTOK * 12;            // scores [8][64]
    __shared__ float sbias[MTOK];
    __shared__ int   smask[MTOK];

    const int r = blockIdx.x;
    const int t = threadIdx.x;

    // ---- load context tile (16384 floats) + Qk row (2048 floats) ----
    {
        const float4* g = (const float4*)(ctx + (size_t)r * (MTOK * DC));
#pragma unroll 4
        for (int i = t; i < MTOK * DC / 4; i += 256) {
            int m  = i >> 6;      // 64 float4 per row
            int c4 = i & 63;
            ((float4*)(ctxs + m * CTX_LD))[c4] = g[i];
        }
        const float4* gq = (const float4*)(g_Qk + (size_t)r * (NHEADS * DC));
#pragma unroll 2
        for (int i = t; i < NHEADS * DC / 4; i += 256)
            ((float4*)qs)[i] = gq[i];
        if (t < MTOK) {
            sbias[t] = bias[(size_t)r * MTOK + t];
            smask[t] = mask[(size_t)r * MTOK + t];
        }
    }
    __syncthreads();

    // ---- scores: thread (m = t&63, h = t>>6 and h+4) ----
    {
        const int m = t & 63;
        const int h = t >> 6;                  // 0..3
        float a0 = 0.0f, a1 = 0.0f;
        const float4* cv = (const float4*)(ctxs + m * CTX_LD);
        const float4* q0 = (const float4*)(qs + h * DC);
        const float4* q1 = (const float4*)(qs + (h + 4) * DC);
#pragma unroll 4
        for (int c = 0; c < DC / 4; c++) {
            float4 cc = cv[c];
            float4 x0 = q0[c];
            float4 x1 = q1[c];
            a0 += cc.x * x0.x + cc.y * x0.y + cc.z * x0.z + cc.w * x0.w;
            a1 += cc.x * x1.x + cc.y * x1.y + cc.z * x1.z + cc.w * x1.w;
        }
        const float bse = sbias[m];
        const bool mk = (smask[m] != 0);
        sc[h * 64 + m]       = mk ? (a0 * 0.125f + bse) : -INFINITY;
        sc[(h + 4) * 64 + m] = mk ? (a1 * 0.125f + bse) : -INFINITY;
    }
    __syncthreads();

    // ---- softmax: warp w handles head h=w; write attn transposed ----
    {
        const int w = t >> 5, lane = t & 31;
        float v0 = sc[w * 64 + lane];
        float v1 = sc[w * 64 + 32 + lane];
        float mx = fmaxf(v0, v1);
#pragma unroll
        for (int o = 16; o; o >>= 1) mx = fmaxf(mx, __shfl_xor_sync(0xffffffffu, mx, o));
        float e0 = __expf(v0 - mx);            // exp(-inf)=0 for masked
        float e1 = __expf(v1 - mx);
        float s = e0 + e1;
#pragma unroll
        for (int o = 16; o; o >>= 1) s += __shfl_xor_sync(0xffffffffu, s, o);
        float inv = 1.0f / s;
        ssT[lane * 12 + w]        = e0 * inv;
        ssT[(lane + 32) * 12 + w] = e1 * inv;
    }
    __syncthreads();

    // ---- ctxA[h][c] = sum_m attn[h][m] * ctx[m][c]; thread owns column c ----
    {
        const int c = t;                       // 0..255
        float acc[NHEADS];
#pragma unroll
        for (int h = 0; h < NHEADS; h++) acc[h] = 0.0f;
#pragma unroll 4
        for (int m = 0; m < MTOK; m++) {
            float cvv = ctxs[m * CTX_LD + c];
            float4 w0 = *(const float4*)(ssT + m * 12);
            float4 w1 = *(const float4*)(ssT + m * 12 + 4);
            acc[0] += w0.x * cvv; acc[1] += w0.y * cvv;
            acc[2] += w0.z * cvv; acc[3] += w0.w * cvv;
            acc[4] += w1.x * cvv; acc[5] += w1.y * cvv;
            acc[6] += w1.z * cvv; acc[7] += w1.w * cvv;
        }
        float* o = g_ctxA + (size_t)r * (NHEADS * DC) + c;
#pragma unroll
        for (int h = 0; h < NHEADS; h++) o[h * DC] = acc[h];
    }
}

// ---------------------------------------------------------------------------
extern "C" void kernel_launch(void* const* d_in, const int* in_sizes, int n_in,
                              void* d_out, int out_size)
{
    const float* x    = (const float*)d_in[0];
    const float* ctx  = (const float*)d_in[1];
    const int*   mask = (const int*)d_in[2];
    const float* bias = (const float*)d_in[3];
    const float* Wq   = (const float*)d_in[4];
    const float* Wk   = (const float*)d_in[5];
    const float* Wv   = (const float*)d_in[6];
    const float* Wo   = (const float*)d_in[7];
    const float* bo   = (const float*)d_in[8];
    float*       out  = (float*)d_out;

    float *Qp, *Qkp, *cAp, *O1p;
    cudaGetSymbolAddress((void**)&Qp,  g_Q);
    cudaGetSymbolAddress((void**)&Qkp, g_Qk);
    cudaGetSymbolAddress((void**)&cAp, g_ctxA);
    cudaGetSymbolAddress((void**)&O1p, g_O1);

    cudaFuncSetAttribute(attn_core,
                         cudaFuncAttributeMaxDynamicSharedMemorySize,
                         ATTN_SMEM_BYTES);

    dim3 blk(256);

    // K1: Q = x @ Wq                 (4096 x 512) * (512 x 512)
    sgemm_k<false, false><<<dim3(DQ / 64, R_TOTAL / 128, 1), blk>>>(
        R_TOTAL, INNER, DQ,
        x,  DQ, 0,
        Wq, INNER, 1, 0,
        Qp, INNER, 0, nullptr);

    // K2: Qk[r,h,c] = sum_d Q[r,h*64+d] * Wk[c, h*64+d]   (batched over h)
    sgemm_k<true, false><<<dim3(DC / 64, R_TOTAL / 128, NHEADS), blk>>>(
        R_TOTAL, DC, DHEAD,
        Qp,  INNER, DHEAD,
        Wk,  1, INNER, DHEAD,
        Qkp, NHEADS * DC, DC, nullptr);

    // K3: fused attention core (context read once)
    attn_core<<<R_TOTAL, 256, ATTN_SMEM_BYTES>>>(ctx, mask, bias);

    // K4: O1[r,h*64+d] = sum_c ctxA[r,h,c] * Wv[c, h*64+d]  (batched over h)
    sgemm_k<false, false><<<dim3(1, R_TOTAL / 128, NHEADS), blk>>>(
        R_TOTAL, DHEAD, DC,
        cAp, NHEADS * DC, DC,
        Wv,  INNER, 1, DHEAD,
        O1p, INNER, DHEAD, nullptr);

    // K5: out = O1 @ Wo + bo
    sgemm_k<false, true><<<dim3(DQ / 64, R_TOTAL / 128, 1), blk>>>(
        R_TOTAL, DQ, INNER,
        O1p, INNER, 0,
        Wo,  DQ, 1, 0,
        out, DQ, 0, bo);
}

// round 4
// speedup vs baseline: 2.1818x; 2.1818x over previous
#include <cuda_runtime.h>
#include <cuda_bf16.h>
#include <math.h>
#include <stdint.h>

// Shapes (fixed)
#define R_TOTAL 4096
#define DQ      512
#define DC      256
#define MTOK    64
#define NHEADS  8
#define DHEAD   64
#define INNER   512

// Scratch (no allocs allowed)
__device__ float g_Q   [R_TOTAL * INNER];
__device__ float g_Qk  [R_TOTAL * NHEADS * DC];
__device__ float g_ctxA[R_TOTAL * NHEADS * DC];
__device__ float g_O1  [R_TOTAL * INNER];
__device__ float g_WqT [INNER * DQ];
__device__ float g_WoT [DQ * INNER];
__device__ float g_WvT [INNER * DC];

// ---------------- helpers ----------------
__device__ __forceinline__ uint32_t smem_u32(const void* p) {
    uint32_t a;
    asm("{ .reg .u64 t; cvta.to.shared.u64 t, %1; cvt.u32.u64 %0, t; }"
        : "=r"(a) : "l"(p));
    return a;
}
__device__ __forceinline__ void ldm_x4(uint32_t* r, uint32_t addr) {
    asm volatile("ldmatrix.sync.aligned.m8n8.x4.shared.b16 {%0,%1,%2,%3}, [%4];"
                 : "=r"(r[0]), "=r"(r[1]), "=r"(r[2]), "=r"(r[3]) : "r"(addr));
}
__device__ __forceinline__ void ldm_x2(uint32_t* r, uint32_t addr) {
    asm volatile("ldmatrix.sync.aligned.m8n8.x2.shared.b16 {%0,%1}, [%2];"
                 : "=r"(r[0]), "=r"(r[1]) : "r"(addr));
}
__device__ __forceinline__ void mma_bf16(float* c, const uint32_t* a, const uint32_t* b) {
    asm volatile("mma.sync.aligned.m16n8k16.row.col.f32.bf16.bf16.f32 "
                 "{%0,%1,%2,%3}, {%4,%5,%6,%7}, {%8,%9}, {%0,%1,%2,%3};"
                 : "+f"(c[0]), "+f"(c[1]), "+f"(c[2]), "+f"(c[3])
                 : "r"(a[0]), "r"(a[1]), "r"(a[2]), "r"(a[3]), "r"(b[0]), "r"(b[1]));
}
__device__ __forceinline__ uint32_t pack2(__nv_bfloat16 a, __nv_bfloat16 b) {
    uint16_t ua = *(uint16_t*)&a, ub = *(uint16_t*)&b;
    return (uint32_t)ua | ((uint32_t)ub << 16);
}
// split float4 -> (hi packed as 2x b32, lo packed as 2x b32)
__device__ __forceinline__ void split_pack(float4 v, uint2& hi, uint2& lo) {
    __nv_bfloat16 hx = __float2bfloat16_rn(v.x);
    __nv_bfloat16 hy = __float2bfloat16_rn(v.y);
    __nv_bfloat16 hz = __float2bfloat16_rn(v.z);
    __nv_bfloat16 hw = __float2bfloat16_rn(v.w);
    __nv_bfloat16 lx = __float2bfloat16_rn(v.x - __bfloat162float(hx));
    __nv_bfloat16 ly = __float2bfloat16_rn(v.y - __bfloat162float(hy));
    __nv_bfloat16 lz = __float2bfloat16_rn(v.z - __bfloat162float(hz));
    __nv_bfloat16 lw = __float2bfloat16_rn(v.w - __bfloat162float(hw));
    hi = make_uint2(pack2(hx, hy), pack2(hz, hw));
    lo = make_uint2(pack2(lx, ly), pack2(lz, lw));
}

// ---------------------------------------------------------------------------
// bf16 3-term mma.sync GEMM: C[m][n] = sum_k A[m][k]*B[n][k] (+bias[n])
// BM=128, BN in {128,64}, BK=32. Row pad 8 bf16 (row = 40 elems = 80B)
// -> conflict-free ldmatrix. Double-buffered smem + register prefetch.
// ---------------------------------------------------------------------------
#define LROW 40                      // bf16 elems per smem row (32 + 8 pad)
#define LROWB 80                     // bytes per row

template<int BN, int MW, int NW, bool BIAS>
__global__ __launch_bounds__(256, 1)
void hgemm(const float* __restrict__ A, int lda, long long bsA,
           const float* __restrict__ B, int ldb, long long bsB,
           float* __restrict__ C, int ldc, long long bsC,
           const float* __restrict__ bias, int K)
{
    constexpr int WM = 128 / MW;
    constexpr int WN = BN / NW;
    constexpr int MT = WM / 16;
    constexpr int NT = WN / 8;
    constexpr int A_BYTES = 128 * LROWB;          // hi region
    constexpr int B_BYTES = BN * LROWB;
    constexpr int STAGE = 2 * A_BYTES + 2 * B_BYTES;

    extern __shared__ char smc[];
    const uint32_t smb = smem_u32(smc);

    const int t = threadIdx.x;
    const int wid = t >> 5, lane = t & 31;
    const int wr = wid / NW, wc = wid % NW;
    const int wm = wr * WM, wn = wc * WN;
    const int bm = blockIdx.y * 128, bn = blockIdx.x * BN;

    A += (long long)blockIdx.z * bsA;
    B += (long long)blockIdx.z * bsB;
    C += (long long)blockIdx.z * bsC;

    const int rloc = t >> 3;          // 0..31
    const int f4   = t & 7;           // 0..7 (float4 column group)

    float acc[MT][NT][4];
#pragma unroll
    for (int i = 0; i < MT; i++)
#pragma unroll
        for (int j = 0; j < NT; j++)
#pragma unroll
            for (int q = 0; q < 4; q++) acc[i][j][q] = 0.0f;

    const int ns = K >> 5;
    float4 pa[4], pb[BN / 32];

    // fragment base byte offsets (within a stage region)
    const uint32_t a_off = (uint32_t)(((wm + (lane & 15)) * LROW + (lane >> 4) * 8) * 2);
    const uint32_t b_off = (uint32_t)(((wn + (lane & 7)) * LROW + ((lane >> 3) & 1) * 8) * 2);

    auto gload = [&](int s) {
#pragma unroll
        for (int i = 0; i < 4; i++)
            pa[i] = *(const float4*)(A + (long long)(bm + rloc + i * 32) * lda + s * 32 + f4 * 4);
#pragma unroll
        for (int i = 0; i < BN / 32; i++)
            pb[i] = *(const float4*)(B + (long long)(bn + rloc + i * 32) * ldb + s * 32 + f4 * 4);
    };
    auto sstore = [&](int buf) {
        char* base = smc + buf * STAGE;
#pragma unroll
        for (int i = 0; i < 4; i++) {
            uint2 hi, lo; split_pack(pa[i], hi, lo);
            int r = rloc + i * 32;
            *(uint2*)(base + r * LROWB + f4 * 8)           = hi;
            *(uint2*)(base + A_BYTES + r * LROWB + f4 * 8) = lo;
        }
        char* bb = base + 2 * A_BYTES;
#pragma unroll
        for (int i = 0; i < BN / 32; i++) {
            uint2 hi, lo; split_pack(pb[i], hi, lo);
            int r = rloc + i * 32;
            *(uint2*)(bb + r * LROWB + f4 * 8)           = hi;
            *(uint2*)(bb + B_BYTES + r * LROWB + f4 * 8) = lo;
        }
    };
    auto compute = [&](int buf) {
        const uint32_t sa = smb + buf * STAGE;
        const uint32_t sb = sa + 2 * A_BYTES;
#pragma unroll
        for (int ks = 0; ks < 2; ks++) {
            uint32_t afh[MT][4], afl[MT][4], bfh[NT][2], bfl[NT][2];
#pragma unroll
            for (int mt = 0; mt < MT; mt++) {
                uint32_t ad = sa + a_off + mt * (16 * LROWB) + ks * 32;
                ldm_x4(afh[mt], ad);
                ldm_x4(afl[mt], ad + A_BYTES);
            }
#pragma unroll
            for (int nt = 0; nt < NT; nt++) {
                uint32_t bd = sb + b_off + nt * (8 * LROWB) + ks * 32;
                ldm_x2(bfh[nt], bd);
                ldm_x2(bfl[nt], bd + B_BYTES);
            }
#pragma unroll
            for (int mt = 0; mt < MT; mt++)
#pragma unroll
                for (int nt = 0; nt < NT; nt++) {
                    mma_bf16(acc[mt][nt], afh[mt], bfh[nt]);
                    mma_bf16(acc[mt][nt], afh[mt], bfl[nt]);
                    mma_bf16(acc[mt][nt], afl[mt], bfh[nt]);
                }
        }
    };

    gload(0);
    sstore(0);
    __syncthreads();
    for (int s = 0; s < ns; s++) {
        if (s + 1 < ns) gload(s + 1);
        compute(s & 1);
        if (s + 1 < ns) {
            sstore((s + 1) & 1);
            __syncthreads();
        }
    }

    // epilogue: mma C layout: c0 (g, 2q), c1 (g, 2q+1), c2 (g+8, 2q), c3 (g+8, 2q+1)
    const int g = lane >> 2, tq = lane & 3;
#pragma unroll
    for (int mt = 0; mt < MT; mt++) {
        int r0 = bm + wm + mt * 16 + g;
#pragma unroll
        for (int nt = 0; nt < NT; nt++) {
            int col = bn + wn + nt * 8 + tq * 2;
            float b0 = 0.f, b1 = 0.f;
            if (BIAS) { b0 = bias[col]; b1 = bias[col + 1]; }
            *(float2*)(C + (long long)r0 * ldc + col) =
                make_float2(acc[mt][nt][0] + b0, acc[mt][nt][1] + b1);
            *(float2*)(C + (long long)(r0 + 8) * ldc + col) =
                make_float2(acc[mt][nt][2] + b0, acc[mt][nt][3] + b1);
        }
    }
}

// ---------------------------------------------------------------------------
// Weight transpose: dst[c*R + r] = src[r*C + c]
// ---------------------------------------------------------------------------
__global__ void transpose_k(const float* __restrict__ src, float* __restrict__ dst,
                            int R, int C)
{
    __shared__ float tile[32][33];
    int bx = blockIdx.x * 32, by = blockIdx.y * 32;
#pragma unroll
    for (int j = 0; j < 32; j += 8)
        tile[threadIdx.y + j][threadIdx.x] =
            src[(long long)(by + threadIdx.y + j) * C + bx + threadIdx.x];
    __syncthreads();
#pragma unroll
    for (int j = 0; j < 32; j += 8)
        dst[(long long)(bx + threadIdx.y + j) * R + by + threadIdx.x] =
            tile[threadIdx.x][threadIdx.y + j];
}

// ---------------------------------------------------------------------------
// Attention core (scalar, round-2 passing version). mask is int32.
// ---------------------------------------------------------------------------
#define CTX_LD 260
#define SMEM_FLOATS (MTOK*CTX_LD + NHEADS*DC + MTOK*12 + NHEADS*MTOK)
#define ATTN_SMEM_BYTES (SMEM_FLOATS * 4)

__global__ __launch_bounds__(256)
void attn_core(const float* __restrict__ ctx,
               const int* __restrict__ mask,
               const float* __restrict__ bias)
{
    extern __shared__ float smf[];
    float* ctxs = smf;
    float* qs   = ctxs + MTOK * CTX_LD;
    float* ssT  = qs + NHEADS * DC;
    float* sc   = ssT + MTOK * 12;
    __shared__ float sbias[MTOK];
    __shared__ int   smask[MTOK];

    const int r = blockIdx.x;
    const int t = threadIdx.x;

    {
        const float4* g = (const float4*)(ctx + (size_t)r * (MTOK * DC));
#pragma unroll 4
        for (int i = t; i < MTOK * DC / 4; i += 256) {
            int m = i >> 6, c4 = i & 63;
            ((float4*)(ctxs + m * CTX_LD))[c4] = g[i];
        }
        const float4* gq = (const float4*)(g_Qk + (size_t)r * (NHEADS * DC));
#pragma unroll 2
        for (int i = t; i < NHEADS * DC / 4; i += 256)
            ((float4*)qs)[i] = gq[i];
        if (t < MTOK) {
            sbias[t] = bias[(size_t)r * MTOK + t];
            smask[t] = mask[(size_t)r * MTOK + t];
        }
    }
    __syncthreads();

    {
        const int m = t & 63;
        const int h = t >> 6;
        float a0 = 0.0f, a1 = 0.0f;
        const float4* cv = (const float4*)(ctxs + m * CTX_LD);
        const float4* q0 = (const float4*)(qs + h * DC);
        const float4* q1 = (const float4*)(qs + (h + 4) * DC);
#pragma unroll 4
        for (int c = 0; c < DC / 4; c++) {
            float4 cc = cv[c];
            float4 x0 = q0[c];
            float4 x1 = q1[c];
            a0 += cc.x * x0.x + cc.y * x0.y + cc.z * x0.z + cc.w * x0.w;
            a1 += cc.x * x1.x + cc.y * x1.y + cc.z * x1.z + cc.w * x1.w;
        }
        const float bse = sbias[m];
        const bool mk = (smask[m] != 0);
        sc[h * 64 + m]       = mk ? (a0 * 0.125f + bse) : -INFINITY;
        sc[(h + 4) * 64 + m] = mk ? (a1 * 0.125f + bse) : -INFINITY;
    }
    __syncthreads();

    {
        const int w = t >> 5, lane = t & 31;
        float v0 = sc[w * 64 + lane];
        float v1 = sc[w * 64 + 32 + lane];
        float mx = fmaxf(v0, v1);
#pragma unroll
        for (int o = 16; o; o >>= 1) mx = fmaxf(mx, __shfl_xor_sync(0xffffffffu, mx, o));
        float e0 = __expf(v0 - mx);
        float e1 = __expf(v1 - mx);
        float s = e0 + e1;
#pragma unroll
        for (int o = 16; o; o >>= 1) s += __shfl_xor_sync(0xffffffffu, s, o);
        float inv = 1.0f / s;
        ssT[lane * 12 + w]        = e0 * inv;
        ssT[(lane + 32) * 12 + w] = e1 * inv;
    }
    __syncthreads();

    {
        const int c = t;
        float acc[NHEADS];
#pragma unroll
        for (int h = 0; h < NHEADS; h++) acc[h] = 0.0f;
#pragma unroll 4
        for (int m = 0; m < MTOK; m++) {
            float cvv = ctxs[m * CTX_LD + c];
            float4 w0 = *(const float4*)(ssT + m * 12);
            float4 w1 = *(const float4*)(ssT + m * 12 + 4);
            acc[0] += w0.x * cvv; acc[1] += w0.y * cvv;
            acc[2] += w0.z * cvv; acc[3] += w0.w * cvv;
            acc[4] += w1.x * cvv; acc[5] += w1.y * cvv;
            acc[6] += w1.z * cvv; acc[7] += w1.w * cvv;
        }
        float* o = g_ctxA + (size_t)r * (NHEADS * DC) + c;
#pragma unroll
        for (int h = 0; h < NHEADS; h++) o[h * DC] = acc[h];
    }
}

// ---------------------------------------------------------------------------
extern "C" void kernel_launch(void* const* d_in, const int* in_sizes, int n_in,
                              void* d_out, int out_size)
{
    const float* x    = (const float*)d_in[0];
    const float* ctx  = (const float*)d_in[1];
    const int*   mask = (const int*)d_in[2];
    const float* bias = (const float*)d_in[3];
    const float* Wq   = (const float*)d_in[4];
    const float* Wk   = (const float*)d_in[5];
    const float* Wv   = (const float*)d_in[6];
    const float* Wo   = (const float*)d_in[7];
    const float* bo   = (const float*)d_in[8];
    float*       out  = (float*)d_out;

    float *Qp, *Qkp, *cAp, *O1p, *WqTp, *WoTp, *WvTp;
    cudaGetSymbolAddress((void**)&Qp,   g_Q);
    cudaGetSymbolAddress((void**)&Qkp,  g_Qk);
    cudaGetSymbolAddress((void**)&cAp,  g_ctxA);
    cudaGetSymbolAddress((void**)&O1p,  g_O1);
    cudaGetSymbolAddress((void**)&WqTp, g_WqT);
    cudaGetSymbolAddress((void**)&WoTp, g_WoT);
    cudaGetSymbolAddress((void**)&WvTp, g_WvT);

    // smem: 2 stages * (2*128*80 + 2*BN*80)
    const int SM128 = 2 * (2 * 128 * LROWB + 2 * 128 * LROWB);   // 81920
    const int SM64  = 2 * (2 * 128 * LROWB + 2 * 64 * LROWB);    // 61440
    cudaFuncSetAttribute((const void*)hgemm<128, 2, 4, false>,
                         cudaFuncAttributeMaxDynamicSharedMemorySize, SM128);
    cudaFuncSetAttribute((const void*)hgemm<128, 2, 4, true>,
                         cudaFuncAttributeMaxDynamicSharedMemorySize, SM128);
    cudaFuncSetAttribute((const void*)hgemm<64, 4, 2, false>,
                         cudaFuncAttributeMaxDynamicSharedMemorySize, SM64);
    cudaFuncSetAttribute((const void*)attn_core,
                         cudaFuncAttributeMaxDynamicSharedMemorySize, ATTN_SMEM_BYTES);

    dim3 tb(32, 8);
    transpose_k<<<dim3(16, 16), tb>>>(Wq, WqTp, DQ, INNER);   // WqT[inner][dq]
    transpose_k<<<dim3(16, 16), tb>>>(Wo, WoTp, INNER, DQ);   // WoT[dq][inner]
    transpose_k<<<dim3(16, 8),  tb>>>(Wv, WvTp, DC, INNER);   // WvT[inner][dc]

    // K1: Q = x @ Wq  : A=x [4096][512], B=WqT [512][512]
    hgemm<128, 2, 4, false><<<dim3(INNER / 128, R_TOTAL / 128, 1), 256, SM128>>>(
        x, DQ, 0, WqTp, DQ, 0, Qp, INNER, 0, nullptr, DQ);

    // K2: Qk[r, h*256+c] = sum_d Q[r, h*64+d] * Wk[c, h*64+d]
    hgemm<128, 2, 4, false><<<dim3(DC / 128, R_TOTAL / 128, NHEADS), 256, SM128>>>(
        Qp, INNER, DHEAD, Wk, INNER, DHEAD, Qkp, NHEADS * DC, DC, nullptr, DHEAD);

    // K3: fused attention core (context read once)
    attn_core<<<R_TOTAL, 256, ATTN_SMEM_BYTES>>>(ctx, mask, bias);

    // K4: O1[r, h*64+d] = sum_c ctxA[r, h*256+c] * WvT[h*64+d, c]
    hgemm<64, 4, 2, false><<<dim3(1, R_TOTAL / 128, NHEADS), 256, SM64>>>(
        cAp, NHEADS * DC, DC, WvTp, DC, (long long)DHEAD * DC,
        O1p, INNER, DHEAD, nullptr, DC);

    // K5: out = O1 @ Wo + bo
    hgemm<128, 2, 4, true><<<dim3(DQ / 128, R_TOTAL / 128, 1), 256, SM128>>>(
        O1p, INNER, 0, WoTp, INNER, 0, out, DQ, 0, bo, INNER);
}

// round 5
// speedup vs baseline: 2.7832x; 1.2756x over previous
#include <cuda_runtime.h>
#include <cuda_bf16.h>
#include <math.h>
#include <stdint.h>

// Shapes (fixed)
#define R_TOTAL 4096
#define DQ      512
#define DC      256
#define MTOK    64
#define NHEADS  8
#define DHEAD   64
#define INNER   512

// Scratch (no allocs allowed)
__device__ float g_Q   [R_TOTAL * INNER];
__device__ float g_Qk  [R_TOTAL * NHEADS * DC];
__device__ float g_ctxA[R_TOTAL * NHEADS * DC];
__device__ float g_O1  [R_TOTAL * INNER];
__device__ float g_WqT [INNER * DQ];
__device__ float g_WoT [DQ * INNER];
__device__ float g_WvT [INNER * DC];

// ---------------- helpers ----------------
__device__ __forceinline__ uint32_t smem_u32(const void* p) {
    uint32_t a;
    asm("{ .reg .u64 t; cvta.to.shared.u64 t, %1; cvt.u32.u64 %0, t; }"
        : "=r"(a) : "l"(p));
    return a;
}
__device__ __forceinline__ void ldm_x4(uint32_t* r, uint32_t addr) {
    asm volatile("ldmatrix.sync.aligned.m8n8.x4.shared.b16 {%0,%1,%2,%3}, [%4];"
                 : "=r"(r[0]), "=r"(r[1]), "=r"(r[2]), "=r"(r[3]) : "r"(addr));
}
__device__ __forceinline__ void ldm_x2(uint32_t* r, uint32_t addr) {
    asm volatile("ldmatrix.sync.aligned.m8n8.x2.shared.b16 {%0,%1}, [%2];"
                 : "=r"(r[0]), "=r"(r[1]) : "r"(addr));
}
__device__ __forceinline__ void ldm_x4_t(uint32_t* r, uint32_t addr) {
    asm volatile("ldmatrix.sync.aligned.m8n8.x4.trans.shared.b16 {%0,%1,%2,%3}, [%4];"
                 : "=r"(r[0]), "=r"(r[1]), "=r"(r[2]), "=r"(r[3]) : "r"(addr));
}
__device__ __forceinline__ void ldm_x2_t(uint32_t* r, uint32_t addr) {
    asm volatile("ldmatrix.sync.aligned.m8n8.x2.trans.shared.b16 {%0,%1}, [%2];"
                 : "=r"(r[0]), "=r"(r[1]) : "r"(addr));
}
__device__ __forceinline__ void mma_bf16(float* c, const uint32_t* a, const uint32_t* b) {
    asm volatile("mma.sync.aligned.m16n8k16.row.col.f32.bf16.bf16.f32 "
                 "{%0,%1,%2,%3}, {%4,%5,%6,%7}, {%8,%9}, {%0,%1,%2,%3};"
                 : "+f"(c[0]), "+f"(c[1]), "+f"(c[2]), "+f"(c[3])
                 : "r"(a[0]), "r"(a[1]), "r"(a[2]), "r"(a[3]), "r"(b[0]), "r"(b[1]));
}
__device__ __forceinline__ uint32_t pack2(__nv_bfloat16 a, __nv_bfloat16 b) {
    uint16_t ua = *(uint16_t*)&a, ub = *(uint16_t*)&b;
    return (uint32_t)ua | ((uint32_t)ub << 16);
}
__device__ __forceinline__ void split_pack(float4 v, uint2& hi, uint2& lo) {
    __nv_bfloat16 hx = __float2bfloat16_rn(v.x);
    __nv_bfloat16 hy = __float2bfloat16_rn(v.y);
    __nv_bfloat16 hz = __float2bfloat16_rn(v.z);
    __nv_bfloat16 hw = __float2bfloat16_rn(v.w);
    __nv_bfloat16 lx = __float2bfloat16_rn(v.x - __bfloat162float(hx));
    __nv_bfloat16 ly = __float2bfloat16_rn(v.y - __bfloat162float(hy));
    __nv_bfloat16 lz = __float2bfloat16_rn(v.z - __bfloat162float(hz));
    __nv_bfloat16 lw = __float2bfloat16_rn(v.w - __bfloat162float(hw));
    hi = make_uint2(pack2(hx, hy), pack2(hz, hw));
    lo = make_uint2(pack2(lx, ly), pack2(lz, lw));
}

// ---------------------------------------------------------------------------
// bf16 3-term mma.sync GEMM (unchanged from round 4)
// ---------------------------------------------------------------------------
#define LROW 40
#define LROWB 80

template<int BN, int MW, int NW, bool BIAS>
__global__ __launch_bounds__(256, 1)
void hgemm(const float* __restrict__ A, int lda, long long bsA,
           const float* __restrict__ B, int ldb, long long bsB,
           float* __restrict__ C, int ldc, long long bsC,
           const float* __restrict__ bias, int K)
{
    constexpr int WM = 128 / MW;
    constexpr int WN = BN / NW;
    constexpr int MT = WM / 16;
    constexpr int NT = WN / 8;
    constexpr int A_BYTES = 128 * LROWB;
    constexpr int B_BYTES = BN * LROWB;
    constexpr int STAGE = 2 * A_BYTES + 2 * B_BYTES;

    extern __shared__ char smc[];
    const uint32_t smb = smem_u32(smc);

    const int t = threadIdx.x;
    const int wid = t >> 5, lane = t & 31;
    const int wr = wid / NW, wc = wid % NW;
    const int wm = wr * WM, wn = wc * WN;
    const int bm = blockIdx.y * 128, bn = blockIdx.x * BN;

    A += (long long)blockIdx.z * bsA;
    B += (long long)blockIdx.z * bsB;
    C += (long long)blockIdx.z * bsC;

    const int rloc = t >> 3;
    const int f4   = t & 7;

    float acc[MT][NT][4];
#pragma unroll
    for (int i = 0; i < MT; i++)
#pragma unroll
        for (int j = 0; j < NT; j++)
#pragma unroll
            for (int q = 0; q < 4; q++) acc[i][j][q] = 0.0f;

    const int ns = K >> 5;
    float4 pa[4], pb[BN / 32];

    const uint32_t a_off = (uint32_t)(((wm + (lane & 15)) * LROW + (lane >> 4) * 8) * 2);
    const uint32_t b_off = (uint32_t)(((wn + (lane & 7)) * LROW + ((lane >> 3) & 1) * 8) * 2);

    auto gload = [&](int s) {
#pragma unroll
        for (int i = 0; i < 4; i++)
            pa[i] = *(const float4*)(A + (long long)(bm + rloc + i * 32) * lda + s * 32 + f4 * 4);
#pragma unroll
        for (int i = 0; i < BN / 32; i++)
            pb[i] = *(const float4*)(B + (long long)(bn + rloc + i * 32) * ldb + s * 32 + f4 * 4);
    };
    auto sstore = [&](int buf) {
        char* base = smc + buf * STAGE;
#pragma unroll
        for (int i = 0; i < 4; i++) {
            uint2 hi, lo; split_pack(pa[i], hi, lo);
            int r = rloc + i * 32;
            *(uint2*)(base + r * LROWB + f4 * 8)           = hi;
            *(uint2*)(base + A_BYTES + r * LROWB + f4 * 8) = lo;
        }
        char* bb = base + 2 * A_BYTES;
#pragma unroll
        for (int i = 0; i < BN / 32; i++) {
            uint2 hi, lo; split_pack(pb[i], hi, lo);
            int r = rloc + i * 32;
            *(uint2*)(bb + r * LROWB + f4 * 8)           = hi;
            *(uint2*)(bb + B_BYTES + r * LROWB + f4 * 8) = lo;
        }
    };
    auto compute = [&](int buf) {
        const uint32_t sa = smb + buf * STAGE;
        const uint32_t sb = sa + 2 * A_BYTES;
#pragma unroll
        for (int ks = 0; ks < 2; ks++) {
            uint32_t afh[MT][4], afl[MT][4], bfh[NT][2], bfl[NT][2];
#pragma unroll
            for (int mt = 0; mt < MT; mt++) {
                uint32_t ad = sa + a_off + mt * (16 * LROWB) + ks * 32;
                ldm_x4(afh[mt], ad);
                ldm_x4(afl[mt], ad + A_BYTES);
            }
#pragma unroll
            for (int nt = 0; nt < NT; nt++) {
                uint32_t bd = sb + b_off + nt * (8 * LROWB) + ks * 32;
                ldm_x2(bfh[nt], bd);
                ldm_x2(bfl[nt], bd + B_BYTES);
            }
#pragma unroll
            for (int mt = 0; mt < MT; mt++)
#pragma unroll
                for (int nt = 0; nt < NT; nt++) {
                    mma_bf16(acc[mt][nt], afh[mt], bfh[nt]);
                    mma_bf16(acc[mt][nt], afh[mt], bfl[nt]);
                    mma_bf16(acc[mt][nt], afl[mt], bfh[nt]);
                }
        }
    };

    gload(0);
    sstore(0);
    __syncthreads();
    for (int s = 0; s < ns; s++) {
        if (s + 1 < ns) gload(s + 1);
        compute(s & 1);
        if (s + 1 < ns) {
            sstore((s + 1) & 1);
            __syncthreads();
        }
    }

    const int g = lane >> 2, tq = lane & 3;
#pragma unroll
    for (int mt = 0; mt < MT; mt++) {
        int r0 = bm + wm + mt * 16 + g;
#pragma unroll
        for (int nt = 0; nt < NT; nt++) {
            int col = bn + wn + nt * 8 + tq * 2;
            float b0 = 0.f, b1 = 0.f;
            if (BIAS) { b0 = bias[col]; b1 = bias[col + 1]; }
            *(float2*)(C + (long long)r0 * ldc + col) =
                make_float2(acc[mt][nt][0] + b0, acc[mt][nt][1] + b1);
            *(float2*)(C + (long long)(r0 + 8) * ldc + col) =
                make_float2(acc[mt][nt][2] + b0, acc[mt][nt][3] + b1);
        }
    }
}

// ---------------------------------------------------------------------------
// Weight transpose
// ---------------------------------------------------------------------------
__global__ void transpose_k(const float* __restrict__ src, float* __restrict__ dst,
                            int R, int C)
{
    __shared__ float tile[32][33];
    int bx = blockIdx.x * 32, by = blockIdx.y * 32;
#pragma unroll
    for (int j = 0; j < 32; j += 8)
        tile[threadIdx.y + j][threadIdx.x] =
            src[(long long)(by + threadIdx.y + j) * C + bx + threadIdx.x];
    __syncthreads();
#pragma unroll
    for (int j = 0; j < 32; j += 8)
        dst[(long long)(bx + threadIdx.y + j) * R + by + threadIdx.x] =
            tile[threadIdx.x][threadIdx.y + j];
}

// ---------------------------------------------------------------------------
// Tensor-core attention core. One CTA per (b,l) row, 256 threads.
//  P1: S[64m][8h] = ctx[64,256] . Qk[8,256]^T   (bf16 3-term mma)
//  softmax over m per head
//  P3: D[256c][8h] = ctx^T[256,64] . attn^T[64,8]  (trans ldmatrix, 3-term)
// ---------------------------------------------------------------------------
#define AC_LDC 528                 // ctx/qk smem row bytes (264 bf16)
#define AC_CH 0
#define AC_CL 33792
#define AC_QH 67584
#define AC_QL 71808
#define AC_AH 76032                // asT hi: 64 rows x 24 bf16 (48 B rows)
#define AC_AL 79104
#define AC_SA 82176                // partial scores 64x9 f32
#define AC_SB 84480
#define AC_BI 86784
#define AC_MK 87040
#define AC_BYTES 87296

__global__ __launch_bounds__(256)
void attn_core(const float* __restrict__ ctx,
               const int* __restrict__ mask,
               const float* __restrict__ bias)
{
    extern __shared__ char sm[];
    const uint32_t smb = smem_u32(sm);
    const int r = blockIdx.x, t = threadIdx.x;
    const int wid = t >> 5, lane = t & 31;

    // ---- phase 0: load + bf16 split ----
    {
        const float4* g = (const float4*)(ctx + (size_t)r * (MTOK * DC));
#pragma unroll
        for (int s = 0; s < 16; s++) {
            int i = t + s * 256;
            int m = i >> 6, c4 = i & 63;
            uint2 hi, lo; split_pack(g[i], hi, lo);
            *(uint2*)(sm + AC_CH + m * AC_LDC + c4 * 8) = hi;
            *(uint2*)(sm + AC_CL + m * AC_LDC + c4 * 8) = lo;
        }
        const float4* gq = (const float4*)(g_Qk + (size_t)r * (NHEADS * DC));
#pragma unroll
        for (int s = 0; s < 2; s++) {
            int i = t + s * 256;
            int h = i >> 6, c4 = i & 63;
            uint2 hi, lo; split_pack(gq[i], hi, lo);
            *(uint2*)(sm + AC_QH + h * AC_LDC + c4 * 8) = hi;
            *(uint2*)(sm + AC_QL + h * AC_LDC + c4 * 8) = lo;
        }
        if (t < MTOK) {
            ((float*)(sm + AC_BI))[t] = bias[(size_t)r * MTOK + t];
            ((int*)(sm + AC_MK))[t]   = mask[(size_t)r * MTOK + t];
        }
    }
    __syncthreads();

    // ---- phase 1: scores. warp w: m-tile (w&3), K-half (w>>2) ----
    {
        const int mtile = wid & 3, khalf = wid >> 2;
        float d[4] = {0.f, 0.f, 0.f, 0.f};
        const uint32_t a_base = smb + AC_CH +
            (uint32_t)((mtile * 16 + (lane & 15)) * AC_LDC + (lane >> 4) * 16);
        const uint32_t b_base = smb + AC_QH +
            (uint32_t)((lane & 7) * AC_LDC + ((lane >> 3) & 1) * 16);
#pragma unroll
        for (int j = 0; j < 8; j++) {
            const int kk = khalf * 8 + j;
            uint32_t ah[4], al[4], bh[2], bl[2];
            ldm_x4(ah, a_base + kk * 32);
            ldm_x4(al, a_base + kk * 32 + (AC_CL - AC_CH));
            ldm_x2(bh, b_base + kk * 32);
            ldm_x2(bl, b_base + kk * 32 + (AC_QL - AC_QH));
            mma_bf16(d, ah, bh);
            mma_bf16(d, ah, bl);
            mma_bf16(d, al, bh);
        }
        float* ss = (float*)(sm + (khalf ? AC_SB : AC_SA));
        const int gg = lane >> 2, tq = lane & 3;
        const int m0 = mtile * 16 + gg;
        ss[m0 * 9 + 2 * tq]           = d[0];
        ss[m0 * 9 + 2 * tq + 1]       = d[1];
        ss[(m0 + 8) * 9 + 2 * tq]     = d[2];
        ss[(m0 + 8) * 9 + 2 * tq + 1] = d[3];
    }
    __syncthreads();

    // ---- softmax: warp w = head h ----
    {
        const int w = wid;
        const float* sa = (const float*)(sm + AC_SA);
        const float* sb = (const float*)(sm + AC_SB);
        const float* sbias = (const float*)(sm + AC_BI);
        const int*   smask = (const int*)(sm + AC_MK);
        const int m0 = lane, m1 = lane + 32;
        float v0 = (sa[m0 * 9 + w] + sb[m0 * 9 + w]) * 0.125f + sbias[m0];
        float v1 = (sa[m1 * 9 + w] + sb[m1 * 9 + w]) * 0.125f + sbias[m1];
        if (!smask[m0]) v0 = -INFINITY;
        if (!smask[m1]) v1 = -INFINITY;
        float mx = fmaxf(v0, v1);
#pragma unroll
        for (int o = 16; o; o >>= 1) mx = fmaxf(mx, __shfl_xor_sync(0xffffffffu, mx, o));
        float e0 = __expf(v0 - mx);
        float e1 = __expf(v1 - mx);
        float s = e0 + e1;
#pragma unroll
        for (int o = 16; o; o >>= 1) s += __shfl_xor_sync(0xffffffffu, s, o);
        float inv = 1.0f / s;
        float a0 = e0 * inv, a1 = e1 * inv;
        __nv_bfloat16 h0 = __float2bfloat16_rn(a0);
        __nv_bfloat16 h1 = __float2bfloat16_rn(a1);
        __nv_bfloat16 l0 = __float2bfloat16_rn(a0 - __bfloat162float(h0));
        __nv_bfloat16 l1 = __float2bfloat16_rn(a1 - __bfloat162float(h1));
        uint16_t* ah = (uint16_t*)(sm + AC_AH);
        uint16_t* al = (uint16_t*)(sm + AC_AL);
        ah[m0 * 24 + w] = *(uint16_t*)&h0;
        ah[m1 * 24 + w] = *(uint16_t*)&h1;
        al[m0 * 24 + w] = *(uint16_t*)&l0;
        al[m1 * 24 + w] = *(uint16_t*)&l1;
    }
    __syncthreads();

    // ---- phase 3: D[c][h], warp w owns c-tiles 2w, 2w+1 ----
    {
        float d0[4] = {0.f, 0.f, 0.f, 0.f};
        float d1[4] = {0.f, 0.f, 0.f, 0.f};
        const int c0 = wid * 32;
        const uint32_t bt_base = smb + AC_AH +
            (uint32_t)((((lane >> 3) & 1) * 8 + (lane & 7)) * 48);
        const uint32_t at_row = (uint32_t)(((lane >> 4) & 1) * 8 + (lane & 7));
        const uint32_t at_col = (uint32_t)(((lane >> 3) & 1) * 16);   // bytes
#pragma unroll
        for (int kk = 0; kk < 4; kk++) {
            uint32_t bh[2], bl[2];
            ldm_x2_t(bh, bt_base + kk * 16 * 48);
            ldm_x2_t(bl, bt_base + kk * 16 * 48 + (AC_AL - AC_AH));
            const uint32_t arow = smb + AC_CH + (kk * 16 + at_row) * AC_LDC + at_col;
            uint32_t ah0[4], al0[4], ah1[4], al1[4];
            ldm_x4_t(ah0, arow + c0 * 2);
            ldm_x4_t(al0, arow + c0 * 2 + (AC_CL - AC_CH));
            ldm_x4_t(ah1, arow + (c0 + 16) * 2);
            ldm_x4_t(al1, arow + (c0 + 16) * 2 + (AC_CL - AC_CH));
            mma_bf16(d0, ah0, bh);
            mma_bf16(d0, ah0, bl);
            mma_bf16(d0, al0, bh);
            mma_bf16(d1, ah1, bh);
            mma_bf16(d1, ah1, bl);
            mma_bf16(d1, al1, bh);
        }
        const int gg = lane >> 2, tq = lane & 3;
        float* o = g_ctxA + (size_t)r * (NHEADS * DC);
        int c = c0 + gg;
        o[(2 * tq) * DC + c]         = d0[0];
        o[(2 * tq + 1) * DC + c]     = d0[1];
        o[(2 * tq) * DC + c + 8]     = d0[2];
        o[(2 * tq + 1) * DC + c + 8] = d0[3];
        c = c0 + 16 + gg;
        o[(2 * tq) * DC + c]         = d1[0];
        o[(2 * tq + 1) * DC + c]     = d1[1];
        o[(2 * tq) * DC + c + 8]     = d1[2];
        o[(2 * tq + 1) * DC + c + 8] = d1[3];
    }
}

// ---------------------------------------------------------------------------
extern "C" void kernel_launch(void* const* d_in, const int* in_sizes, int n_in,
                              void* d_out, int out_size)
{
    const float* x    = (const float*)d_in[0];
    const float* ctx  = (const float*)d_in[1];
    const int*   mask = (const int*)d_in[2];
    const float* bias = (const float*)d_in[3];
    const float* Wq   = (const float*)d_in[4];
    const float* Wk   = (const float*)d_in[5];
    const float* Wv   = (const float*)d_in[6];
    const float* Wo   = (const float*)d_in[7];
    const float* bo   = (const float*)d_in[8];
    float*       out  = (float*)d_out;

    float *Qp, *Qkp, *cAp, *O1p, *WqTp, *WoTp, *WvTp;
    cudaGetSymbolAddress((void**)&Qp,   g_Q);
    cudaGetSymbolAddress((void**)&Qkp,  g_Qk);
    cudaGetSymbolAddress((void**)&cAp,  g_ctxA);
    cudaGetSymbolAddress((void**)&O1p,  g_O1);
    cudaGetSymbolAddress((void**)&WqTp, g_WqT);
    cudaGetSymbolAddress((void**)&WoTp, g_WoT);
    cudaGetSymbolAddress((void**)&WvTp, g_WvT);

    const int SM128 = 2 * (2 * 128 * LROWB + 2 * 128 * LROWB);
    const int SM64  = 2 * (2 * 128 * LROWB + 2 * 64 * LROWB);
    cudaFuncSetAttribute((const void*)hgemm<128, 2, 4, false>,
                         cudaFuncAttributeMaxDynamicSharedMemorySize, SM128);
    cudaFuncSetAttribute((const void*)hgemm<128, 2, 4, true>,
                         cudaFuncAttributeMaxDynamicSharedMemorySize, SM128);
    cudaFuncSetAttribute((const void*)hgemm<64, 4, 2, false>,
                         cudaFuncAttributeMaxDynamicSharedMemorySize, SM64);
    cudaFuncSetAttribute((const void*)attn_core,
                         cudaFuncAttributeMaxDynamicSharedMemorySize, AC_BYTES);

    dim3 tb(32, 8);
    transpose_k<<<dim3(16, 16), tb>>>(Wq, WqTp, DQ, INNER);
    transpose_k<<<dim3(16, 16), tb>>>(Wo, WoTp, INNER, DQ);
    transpose_k<<<dim3(16, 8),  tb>>>(Wv, WvTp, DC, INNER);

    // K1: Q = x @ Wq
    hgemm<128, 2, 4, false><<<dim3(INNER / 128, R_TOTAL / 128, 1), 256, SM128>>>(
        x, DQ, 0, WqTp, DQ, 0, Qp, INNER, 0, nullptr, DQ);

    // K2: Qk[r, h*256+c] = sum_d Q[r, h*64+d] * Wk[c, h*64+d]
    hgemm<128, 2, 4, false><<<dim3(DC / 128, R_TOTAL / 128, NHEADS), 256, SM128>>>(
        Qp, INNER, DHEAD, Wk, INNER, DHEAD, Qkp, NHEADS * DC, DC, nullptr, DHEAD);

    // K3: fused attention core (tensor cores)
    attn_core<<<R_TOTAL, 256, AC_BYTES>>>(ctx, mask, bias);

    // K4: O1[r, h*64+d] = sum_c ctxA[r, h*256+c] * WvT[h*64+d, c]
    hgemm<64, 4, 2, false><<<dim3(1, R_TOTAL / 128, NHEADS), 256, SM64>>>(
        cAp, NHEADS * DC, DC, WvTp, DC, (long long)DHEAD * DC,
        O1p, INNER, DHEAD, nullptr, DC);

    // K5: out = O1 @ Wo + bo
    hgemm<128, 2, 4, true><<<dim3(DQ / 128, R_TOTAL / 128, 1), 256, SM128>>>(
        O1p, INNER, 0, WoTp, INNER, 0, out, DQ, 0, bo, INNER);
}